// round 4
// baseline (speedup 1.0000x reference)
#include <cuda_runtime.h>
#include <cuda_bf16.h>
#include <math.h>

#define NTRAJ  256
#define NTP    512
#define LATENT 256
#define INPUT  128
#define NUNITS 256
#define GIN    (LATENT + INPUT)   // 384
#define DEC_OUT 128
#define NSTEP  (NTP - 1)          // 511

#define G     4                   // trajectories per block
#define NBLK  (NTRAJ / G)         // 64 blocks
#define THREADS 512               // split-K x2 (x4 for decoder)

typedef unsigned long long u64;

union F2U { float2 f; u64 u; };

__device__ __forceinline__ u64 ffma2(u64 a, u64 b, u64 c) {
    u64 d;
    asm("fma.rn.f32x2 %0, %1, %2, %3;" : "=l"(d) : "l"(a), "l"(b), "l"(c));
    return d;
}

__device__ __forceinline__ float lanesum(u64 v) {
    F2U r; r.u = v; return r.f.x + r.f.y;
}

__device__ __forceinline__ float sigmoid_fast(float x) {
    return __fdividef(1.f, 1.f + __expf(-x));
}

// ---------------------------------------------------------------------------
// Packed weights: float4 along k: W4[k4][j] = W[4k4..4k4+3][j], as ulonglong2.
// ---------------------------------------------------------------------------
#define SZ_M384 (96 * 256)
#define SZ_M256 (64 * 256)
#define SZ_DEC  (64 * 128)
#define OFF_UG1  0
#define OFF_UGT1 (OFF_UG1  + SZ_M384)
#define OFF_RG1  (OFF_UGT1 + SZ_M384)
#define OFF_NS1  (OFF_RG1  + SZ_M384)
#define OFF_UG2  (OFF_NS1  + SZ_M384)
#define OFF_UGT2 (OFF_UG2  + SZ_M256)
#define OFF_RG2  (OFF_UGT2 + SZ_M256)
#define OFF_NS2  (OFF_RG2  + SZ_M256)
#define OFF_DK1  (OFF_NS2  + SZ_M256)
#define OFF_DEC  (OFF_DK1  + SZ_M256)
#define WP_TOTAL (OFF_DEC  + SZ_DEC)

__device__ ulonglong2 g_wp[WP_TOTAL];

__global__ void pack_kernel(
    const float* ug1, const float* ugt1, const float* rg1, const float* ns1,
    const float* ug2, const float* ugt2, const float* rg2, const float* ns2,
    const float* dk1, const float* decw)
{
    const float* srcs[10] = {ug1, ugt1, rg1, ns1, ug2, ugt2, rg2, ns2, dk1, decw};
    const int offs[11] = {OFF_UG1, OFF_UGT1, OFF_RG1, OFF_NS1, OFF_UG2, OFF_UGT2,
                          OFF_RG2, OFF_NS2, OFF_DK1, OFF_DEC, WP_TOTAL};
    const int Ns[10] = {256,256,256,256,256,256,256,256,256,128};

    int idx = blockIdx.x * blockDim.x + threadIdx.x;
    if (idx >= WP_TOTAL) return;
    int m = 0;
    while (idx >= offs[m + 1]) m++;
    int local = idx - offs[m];
    int N = Ns[m];
    int k4 = local / N, j = local % N;
    const float* S = srcs[m];
    F2U lo, hi;
    lo.f = make_float2(S[(4 * k4 + 0) * N + j], S[(4 * k4 + 1) * N + j]);
    hi.f = make_float2(S[(4 * k4 + 2) * N + j], S[(4 * k4 + 3) * N + j]);
    g_wp[idx] = make_ulonglong2(lo.u, hi.u);
}

// ---------------------------------------------------------------------------
// Partial packed GEMV over one k-slice (no bias), depth-D register pipeline.
// K2H = k-pairs in slice, NG matrices sharing one activation input,
// N = output width, CU = k4-rows per chunk, D = pipeline depth (chunks).
// ---------------------------------------------------------------------------
template <int K2H, int NG, int N, int CU, int D>
__device__ __forceinline__ void gemv_part(
    float (&res)[NG][G],
    const ulonglong2* const (&Wv)[NG],
    const float* act, int astride, int j)
{
    constexpr int K4 = K2H / 2;
    constexpr int CH = K4 / CU;
    constexpr int DD = (D < CH) ? D : CH;

    u64 acc[NG][G];
#pragma unroll
    for (int ng = 0; ng < NG; ng++)
#pragma unroll
        for (int g = 0; g < G; g++) acc[ng][g] = 0ull;

    ulonglong2 w[DD][NG][CU];
#pragma unroll
    for (int d = 0; d < DD; d++)
#pragma unroll
        for (int ng = 0; ng < NG; ng++)
#pragma unroll
            for (int cu = 0; cu < CU; cu++)
                w[d][ng][cu] = Wv[ng][(d * CU + cu) * N + j];

#pragma unroll
    for (int c = 0; c < CH; c++) {
        const int slot = c % DD;
#pragma unroll
        for (int cu = 0; cu < CU; cu++) {
            int k4 = c * CU + cu;
            u64 a0[G], a1[G];
#pragma unroll
            for (int g = 0; g < G; g++) {
                ulonglong2 av = *(const ulonglong2*)(act + g * astride + 4 * k4);
                a0[g] = av.x; a1[g] = av.y;
            }
#pragma unroll
            for (int ng = 0; ng < NG; ng++)
#pragma unroll
                for (int g = 0; g < G; g++) {
                    acc[ng][g] = ffma2(a0[g], w[slot][ng][cu].x, acc[ng][g]);
                    acc[ng][g] = ffma2(a1[g], w[slot][ng][cu].y, acc[ng][g]);
                }
        }
        if (c + DD < CH) {
#pragma unroll
            for (int ng = 0; ng < NG; ng++)
#pragma unroll
                for (int cu = 0; cu < CU; cu++)
                    w[slot][ng][cu] = Wv[ng][((c + DD) * CU + cu) * N + j];
        }
    }

#pragma unroll
    for (int ng = 0; ng < NG; ng++)
#pragma unroll
        for (int g = 0; g < G; g++) res[ng][g] = lanesum(acc[ng][g]);
}

__global__ __launch_bounds__(THREADS, 1)
void rnn_decay_kernel(
    const float* __restrict__ data, const float* __restrict__ ts,
    const float* __restrict__ ug_b1,  const float* __restrict__ ug_b2,
    const float* __restrict__ ugt_b1, const float* __restrict__ ugt_b2,
    const float* __restrict__ rg_b1,  const float* __restrict__ rg_b2,
    const float* __restrict__ ns_b1,  const float* __restrict__ ns_b2,
    const float* __restrict__ dk_b1,  const float* __restrict__ dk_w2,
    const float* __restrict__ dk_b2,  const float* __restrict__ dec_b,
    float* __restrict__ out)
{
    __shared__ __align__(16) float sy [G * LATENT];
    __shared__ __align__(16) float syt[G * LATENT];
    __shared__ __align__(16) float syc[G * GIN];
    __shared__ __align__(16) float shh0[G * NUNITS];
    __shared__ __align__(16) float shh1[G * NUNITS];
    __shared__ __align__(16) float shh2[G * NUNITS];
    __shared__ __align__(16) float sc[3][G][256];   // cross-half partials
    __shared__ float sdt[G], sdecay[G], smask[G];
    __shared__ float sred[8][G];

    float* scd = &sc[0][0][0];   // decoder view: [q][g][128]

    const int tid  = threadIdx.x;
    const int j    = tid & 255;          // output unit for 256-wide gemvs
    const int half = tid >> 8;           // k-half
    const int lane = tid & 31, warp = tid >> 5;
    const int tb   = blockIdx.x * G;
    const int gA   = half * 2;           // own trajectory pair start
    const int gO   = 2 - gA;             // other pair start

    const ulonglong2* WP = g_wp;

    float* out_prev = out;
    float* out_vol  = out + (size_t)NTRAJ * LATENT;
    float* out_dts  = out + (size_t)NTRAJ * LATENT + (size_t)NTRAJ * NSTEP * DEC_OUT;

    for (int i = tid; i < G * LATENT; i += THREADS) { sy[i] = 0.f; syt[i] = 0.f; }

    for (int t = 0; t < NTP; t++) {
        __syncthreads();

        // ---- setup: xh -> syc tail, mask, dt ----
        {
            int g = tid >> 7, jj = tid & 127;
            syc[g * GIN + LATENT + jj] =
                data[((size_t)(tb + g) * NTP + t) * (2 * INPUT) + jj];
        }
        if (warp < G) {
            const float* xp = data + ((size_t)(tb + warp) * NTP + t) * (2 * INPUT) + INPUT;
            float s = xp[lane] + xp[lane + 32] + xp[lane + 64] + xp[lane + 96];
#pragma unroll
            for (int off = 16; off; off >>= 1) s += __shfl_xor_sync(0xffffffffu, s, off);
            if (lane == 0) smask[warp] = (s > 0.f) ? 1.f : 0.f;
        }
        if (tid < G && t > 0) {
            float d = ts[(size_t)(tb + tid) * NTP + t] - ts[(size_t)(tb + tid) * NTP + t - 1];
            sdt[tid] = d;
            out_dts[(size_t)(tb + tid) * NSTEP + (t - 1)] = d;
        }
        __syncthreads();

        if (t > 0) {
            // ---- decay layer1 (256->256), split-K x2, split-g combine ----
            {
                const ulonglong2* Wd[1] = { WP + OFF_DK1 + half * 32 * 256 };
                float p[1][G];
                gemv_part<64, 1, 256, 2, 4>(p, Wd, sy + half * 128, LATENT, j);
                float bv = dk_b1[j];
                sc[0][gO + 0][j] = p[0][gO + 0];
                sc[0][gO + 1][j] = p[0][gO + 1];
                __syncthreads();
#pragma unroll
                for (int gg = 0; gg < 2; gg++) {
                    int g = gA + gg;
                    shh0[g * NUNITS + j] = fmaxf(p[0][g] + sc[0][g][j] + bv, 0.f);
                }
                __syncthreads();
            }
            // ---- decay layer2: 256 -> 1 (half 0 warps) ----
            if (!half) {
                float v[G];
                float w2v = dk_w2[j];
#pragma unroll
                for (int g = 0; g < G; g++) v[g] = shh0[g * NUNITS + j] * w2v;
#pragma unroll
                for (int off = 16; off; off >>= 1)
#pragma unroll
                    for (int g = 0; g < G; g++) v[g] += __shfl_xor_sync(0xffffffffu, v[g], off);
                if (lane == 0)
#pragma unroll
                    for (int g = 0; g < G; g++) sred[warp][g] = v[g];
            }
            __syncthreads();
            if (tid < G) {
                float s = dk_b2[0];
#pragma unroll
                for (int w = 0; w < 8; w++) s += sred[w][tid];
                sdecay[tid] = fmaxf(s, 0.f);
            }
            __syncthreads();

            // ---- elementwise decay (own pair): mean_ydec -> shh0, y_end -> sy/syc ----
#pragma unroll
            for (int gg = 0; gg < 2; gg++) {
                int g = gA + gg;
                float d  = sdecay[g] * sdt[g];
                float e1 = __expf(-0.5f * d);
                float e2 = __expf(-d);
                float yv = sy[g * LATENT + j], ytv = syt[g * LATENT + j];
                float df = yv - ytv;
                shh0[g * NUNITS + j] = ytv + df * (0.5f * (1.f + e1));
                float yend = ytv + df * e2;
                sy[g * LATENT + j] = yend;
                syc[g * GIN + j]   = yend;
            }
            __syncthreads();

            // ---- vol decoder (256->128), split-K x4, two combiner quarters ----
            {
                int q = tid >> 7, jd = tid & 127;
                const ulonglong2* Wd[1] = { WP + OFF_DEC + q * 16 * 128 };
                float p[1][G];
                gemv_part<32, 1, 128, 2, 4>(p, Wd, shh0 + q * 64, NUNITS, jd);
                float bv = dec_b[jd];
#pragma unroll
                for (int g = 0; g < G; g++) scd[(q * G + g) * 128 + jd] = p[0][g];
                __syncthreads();
                if (q <= 1) {
#pragma unroll
                    for (int gg = 0; gg < 2; gg++) {
                        int g = q * 2 + gg;
                        float v = p[0][g] + bv;
#pragma unroll
                        for (int qq = 0; qq < 4; qq++)
                            if (qq != q) v += scd[(qq * G + g) * 128 + jd];
                        out_vol[((size_t)(tb + g) * NSTEP + (t - 1)) * DEC_OUT + jd] = v;
                    }
                }
            }
        } else {
#pragma unroll
            for (int gg = 0; gg < 2; gg++) syc[(gA + gg) * GIN + j] = 0.f;
        }
        __syncthreads();

        // ---- fused gate layer1: ug/ugt/rg (384->256 x3) ----
        {
            const ulonglong2* Wg[3] = { WP + OFF_UG1  + half * 48 * 256,
                                        WP + OFF_UGT1 + half * 48 * 256,
                                        WP + OFF_RG1  + half * 48 * 256 };
            float p[3][G];
            gemv_part<96, 3, 256, 1, 3>(p, Wg, syc + half * 192, GIN, j);
            float b0 = ug_b1[j], b1 = ugt_b1[j], b2 = rg_b1[j];
#pragma unroll
            for (int ng = 0; ng < 3; ng++) {
                sc[ng][gO + 0][j] = p[ng][gO + 0];
                sc[ng][gO + 1][j] = p[ng][gO + 1];
            }
            __syncthreads();
#pragma unroll
            for (int gg = 0; gg < 2; gg++) {
                int g = gA + gg;
                shh0[g * NUNITS + j] = tanhf(p[0][g] + sc[0][g][j] + b0);
                shh1[g * NUNITS + j] = tanhf(p[1][g] + sc[1][g][j] + b1);
                shh2[g * NUNITS + j] = tanhf(p[2][g] + sc[2][g][j] + b2);
            }
            __syncthreads();
        }

        // ---- gate layer2 x3 (256->256), batched partials, split-g combine ----
        float u2[2], ut2[2];
        {
            const ulonglong2* W0[1] = { WP + OFF_UG2  + half * 32 * 256 };
            const ulonglong2* W1[1] = { WP + OFF_UGT2 + half * 32 * 256 };
            const ulonglong2* W2[1] = { WP + OFF_RG2  + half * 32 * 256 };
            float p0[1][G], p1[1][G], p2[1][G];
            gemv_part<64, 1, 256, 2, 4>(p0, W0, shh0 + half * 128, NUNITS, j);
            gemv_part<64, 1, 256, 2, 4>(p1, W1, shh1 + half * 128, NUNITS, j);
            gemv_part<64, 1, 256, 2, 4>(p2, W2, shh2 + half * 128, NUNITS, j);
            float b0 = ug_b2[j], b1 = ugt_b2[j], b2 = rg_b2[j];
#pragma unroll
            for (int gg = 0; gg < 2; gg++) {
                int g = gO + gg;
                sc[0][g][j] = p0[0][g];
                sc[1][g][j] = p1[0][g];
                sc[2][g][j] = p2[0][g];
            }
            __syncthreads();
#pragma unroll
            for (int gg = 0; gg < 2; gg++) {
                int g = gA + gg;
                u2[gg]  = sigmoid_fast(p0[0][g] + sc[0][g][j] + b0);
                ut2[gg] = sigmoid_fast(p1[0][g] + sc[1][g][j] + b1);
                syc[g * GIN + j] *= sigmoid_fast(p2[0][g] + sc[2][g][j] + b2);
            }
            __syncthreads();
        }

        // ---- new_state layer1 (384->256) ----
        {
            const ulonglong2* Wg[1] = { WP + OFF_NS1 + half * 48 * 256 };
            float p[1][G];
            gemv_part<96, 1, 256, 2, 4>(p, Wg, syc + half * 192, GIN, j);
            float bv = ns_b1[j];
            sc[0][gO + 0][j] = p[0][gO + 0];
            sc[0][gO + 1][j] = p[0][gO + 1];
            __syncthreads();
#pragma unroll
            for (int gg = 0; gg < 2; gg++) {
                int g = gA + gg;
                shh0[g * NUNITS + j] = tanhf(p[0][g] + sc[0][g][j] + bv);
            }
            __syncthreads();
        }

        // ---- new_state layer2 (256->256) + masked state update ----
        {
            const ulonglong2* Wg[1] = { WP + OFF_NS2 + half * 32 * 256 };
            float p[1][G];
            gemv_part<64, 1, 256, 2, 4>(p, Wg, shh0 + half * 128, NUNITS, j);
            float bv = ns_b2[j];
            sc[0][gO + 0][j] = p[0][gO + 0];
            sc[0][gO + 1][j] = p[0][gO + 1];
            __syncthreads();
#pragma unroll
            for (int gg = 0; gg < 2; gg++) {
                int g = gA + gg;
                float nsv  = p[0][g] + sc[0][g][j] + bv;
                float m    = smask[g];
                float yend = sy[g * LATENT + j], ytv = syt[g * LATENT + j];
                float ny   = (1.f - u2[gg])  * nsv + u2[gg]  * yend;
                float nyt  = (1.f - ut2[gg]) * nsv + ut2[gg] * ytv;
                sy [g * LATENT + j] = m * ny  + (1.f - m) * yend;
                syt[g * LATENT + j] = m * nyt + (1.f - m) * ytv;
            }
        }
        // top-of-loop sync protects sy/syt writes
    }

    __syncthreads();
#pragma unroll
    for (int gg = 0; gg < 2; gg++) {
        int g = gA + gg;
        out_prev[(size_t)(tb + g) * LATENT + j] = sy[g * LATENT + j];
    }
}

extern "C" void kernel_launch(void* const* d_in, const int* in_sizes, int n_in,
                              void* d_out, int out_size) {
    const float* data   = (const float*)d_in[0];
    const float* ts     = (const float*)d_in[1];
    const float* ug_w1  = (const float*)d_in[2];
    const float* ug_b1  = (const float*)d_in[3];
    const float* ug_w2  = (const float*)d_in[4];
    const float* ug_b2  = (const float*)d_in[5];
    const float* ugt_w1 = (const float*)d_in[6];
    const float* ugt_b1 = (const float*)d_in[7];
    const float* ugt_w2 = (const float*)d_in[8];
    const float* ugt_b2 = (const float*)d_in[9];
    const float* rg_w1  = (const float*)d_in[10];
    const float* rg_b1  = (const float*)d_in[11];
    const float* rg_w2  = (const float*)d_in[12];
    const float* rg_b2  = (const float*)d_in[13];
    // d_in[14..17] = rgt_* : unused by the reference
    const float* ns_w1  = (const float*)d_in[18];
    const float* ns_b1  = (const float*)d_in[19];
    const float* ns_w2  = (const float*)d_in[20];
    const float* ns_b2  = (const float*)d_in[21];
    const float* dk_w1  = (const float*)d_in[22];
    const float* dk_b1  = (const float*)d_in[23];
    const float* dk_w2  = (const float*)d_in[24];
    const float* dk_b2  = (const float*)d_in[25];
    const float* dec_w  = (const float*)d_in[26];
    const float* dec_b  = (const float*)d_in[27];

    pack_kernel<<<(WP_TOTAL + 255) / 256, 256>>>(
        ug_w1, ugt_w1, rg_w1, ns_w1, ug_w2, ugt_w2, rg_w2, ns_w2, dk_w1, dec_w);

    rnn_decay_kernel<<<NBLK, THREADS>>>(
        data, ts,
        ug_b1, ug_b2, ugt_b1, ugt_b2, rg_b1, rg_b2,
        ns_b1, ns_b2, dk_b1, dk_w2, dk_b2, dec_b,
        (float*)d_out);
}

// round 5
// speedup vs baseline: 1.5467x; 1.5467x over previous
#include <cuda_runtime.h>
#include <cuda_bf16.h>
#include <math.h>

#define NTRAJ  256
#define NTP    512
#define LATENT 256
#define INPUT  128
#define NUNITS 256
#define GIN    (LATENT + INPUT)   // 384
#define DEC_OUT 128
#define NSTEP  (NTP - 1)          // 511

#define G     4                   // trajectories per block
#define NBLK  (NTRAJ / G)         // 64 blocks
#define THREADS 512               // split-K x2 (x4 for decoder)

typedef unsigned long long u64;

union F2U { float2 f; u64 u; };

__device__ __forceinline__ u64 ffma2(u64 a, u64 b, u64 c) {
    u64 d;
    asm("fma.rn.f32x2 %0, %1, %2, %3;" : "=l"(d) : "l"(a), "l"(b), "l"(c));
    return d;
}

__device__ __forceinline__ float lanesum(u64 v) {
    F2U r; r.u = v; return r.f.x + r.f.y;
}

__device__ __forceinline__ float sigmoid_fast(float x) {
    return __fdividef(1.f, 1.f + __expf(-x));
}

// ---------------------------------------------------------------------------
// Packed weights: float4 along k: W4[k4][j] = W[4k4..4k4+3][j], as ulonglong2.
// ---------------------------------------------------------------------------
#define SZ_M384 (96 * 256)
#define SZ_M256 (64 * 256)
#define SZ_DEC  (64 * 128)
#define OFF_UG1  0
#define OFF_UGT1 (OFF_UG1  + SZ_M384)
#define OFF_RG1  (OFF_UGT1 + SZ_M384)
#define OFF_NS1  (OFF_RG1  + SZ_M384)
#define OFF_UG2  (OFF_NS1  + SZ_M384)
#define OFF_UGT2 (OFF_UG2  + SZ_M256)
#define OFF_RG2  (OFF_UGT2 + SZ_M256)
#define OFF_NS2  (OFF_RG2  + SZ_M256)
#define OFF_DK1  (OFF_NS2  + SZ_M256)
#define OFF_DEC  (OFF_DK1  + SZ_M256)
#define WP_TOTAL (OFF_DEC  + SZ_DEC)

__device__ ulonglong2 g_wp[WP_TOTAL];

__global__ void pack_kernel(
    const float* ug1, const float* ugt1, const float* rg1, const float* ns1,
    const float* ug2, const float* ugt2, const float* rg2, const float* ns2,
    const float* dk1, const float* decw)
{
    const float* srcs[10] = {ug1, ugt1, rg1, ns1, ug2, ugt2, rg2, ns2, dk1, decw};
    const int offs[11] = {OFF_UG1, OFF_UGT1, OFF_RG1, OFF_NS1, OFF_UG2, OFF_UGT2,
                          OFF_RG2, OFF_NS2, OFF_DK1, OFF_DEC, WP_TOTAL};
    const int Ns[10] = {256,256,256,256,256,256,256,256,256,128};

    int idx = blockIdx.x * blockDim.x + threadIdx.x;
    if (idx >= WP_TOTAL) return;
    int m = 0;
    while (idx >= offs[m + 1]) m++;
    int local = idx - offs[m];
    int N = Ns[m];
    int k4 = local / N, j = local % N;
    const float* S = srcs[m];
    F2U lo, hi;
    lo.f = make_float2(S[(4 * k4 + 0) * N + j], S[(4 * k4 + 1) * N + j]);
    hi.f = make_float2(S[(4 * k4 + 2) * N + j], S[(4 * k4 + 3) * N + j]);
    g_wp[idx] = make_ulonglong2(lo.u, hi.u);
}

// ---------------------------------------------------------------------------
// Partial packed GEMV, shared activation input (no bias; combine adds it).
// Explicit A/B double-buffer (NO dynamic register-array indexing).
// ---------------------------------------------------------------------------
template <int K2H, int NG, int N, int CU>
__device__ __forceinline__ void gemv_part(
    float (&res)[NG][G],
    const ulonglong2* const (&Wv)[NG],
    const float* act, int astride, int j)
{
    constexpr int K4 = K2H / 2;
    constexpr int CH = K4 / CU;
    static_assert(CH % 2 == 0, "chunks must be even");

    u64 acc[NG][G];
#pragma unroll
    for (int ng = 0; ng < NG; ng++)
#pragma unroll
        for (int g = 0; g < G; g++) acc[ng][g] = 0ull;

    ulonglong2 wA[NG][CU], wB[NG][CU];

    auto LD = [&](ulonglong2 (&w)[NG][CU], int c) {
#pragma unroll
        for (int ng = 0; ng < NG; ng++)
#pragma unroll
            for (int cu = 0; cu < CU; cu++)
                w[ng][cu] = Wv[ng][(c * CU + cu) * N + j];
    };
    auto CP = [&](ulonglong2 (&w)[NG][CU], int c) {
#pragma unroll
        for (int cu = 0; cu < CU; cu++) {
            int k4 = c * CU + cu;
            u64 a0[G], a1[G];
#pragma unroll
            for (int g = 0; g < G; g++) {
                ulonglong2 av = *(const ulonglong2*)(act + g * astride + 4 * k4);
                a0[g] = av.x; a1[g] = av.y;
            }
#pragma unroll
            for (int ng = 0; ng < NG; ng++)
#pragma unroll
                for (int g = 0; g < G; g++) {
                    acc[ng][g] = ffma2(a0[g], w[ng][cu].x, acc[ng][g]);
                    acc[ng][g] = ffma2(a1[g], w[ng][cu].y, acc[ng][g]);
                }
        }
    };

    LD(wA, 0);
#pragma unroll 1
    for (int cc = 0; cc < CH / 2; cc++) {
        LD(wB, 2 * cc + 1);
        CP(wA, 2 * cc);
        if (cc + 1 < CH / 2) LD(wA, 2 * cc + 2);
        CP(wB, 2 * cc + 1);
    }

#pragma unroll
    for (int ng = 0; ng < NG; ng++)
#pragma unroll
        for (int g = 0; g < G; g++) res[ng][g] = lanesum(acc[ng][g]);
}

// ---------------------------------------------------------------------------
// Same, but each matrix has its OWN activation input (gate-layer-2 fusion).
// CU = 1 to bound register pressure.
// ---------------------------------------------------------------------------
template <int K2H, int NG, int N>
__device__ __forceinline__ void gemv_part_ma(
    float (&res)[NG][G],
    const ulonglong2* const (&Wv)[NG],
    const float* const (&av)[NG], int astride, int j)
{
    constexpr int K4 = K2H / 2;
    constexpr int CH = K4;
    static_assert(CH % 2 == 0, "chunks must be even");

    u64 acc[NG][G];
#pragma unroll
    for (int ng = 0; ng < NG; ng++)
#pragma unroll
        for (int g = 0; g < G; g++) acc[ng][g] = 0ull;

    ulonglong2 wA[NG], wB[NG];

    auto LD = [&](ulonglong2 (&w)[NG], int c) {
#pragma unroll
        for (int ng = 0; ng < NG; ng++)
            w[ng] = Wv[ng][c * N + j];
    };
    auto CP = [&](ulonglong2 (&w)[NG], int c) {
#pragma unroll
        for (int ng = 0; ng < NG; ng++) {
#pragma unroll
            for (int g = 0; g < G; g++) {
                ulonglong2 avv = *(const ulonglong2*)(av[ng] + g * astride + 4 * c);
                acc[ng][g] = ffma2(avv.x, w[ng].x, acc[ng][g]);
                acc[ng][g] = ffma2(avv.y, w[ng].y, acc[ng][g]);
            }
        }
    };

    LD(wA, 0);
#pragma unroll 1
    for (int cc = 0; cc < CH / 2; cc++) {
        LD(wB, 2 * cc + 1);
        CP(wA, 2 * cc);
        if (cc + 1 < CH / 2) LD(wA, 2 * cc + 2);
        CP(wB, 2 * cc + 1);
    }

#pragma unroll
    for (int ng = 0; ng < NG; ng++)
#pragma unroll
        for (int g = 0; g < G; g++) res[ng][g] = lanesum(acc[ng][g]);
}

__global__ __launch_bounds__(THREADS, 1)
void rnn_decay_kernel(
    const float* __restrict__ data, const float* __restrict__ ts,
    const float* __restrict__ ug_b1,  const float* __restrict__ ug_b2,
    const float* __restrict__ ugt_b1, const float* __restrict__ ugt_b2,
    const float* __restrict__ rg_b1,  const float* __restrict__ rg_b2,
    const float* __restrict__ ns_b1,  const float* __restrict__ ns_b2,
    const float* __restrict__ dk_b1,  const float* __restrict__ dk_w2,
    const float* __restrict__ dk_b2,  const float* __restrict__ dec_b,
    float* __restrict__ out)
{
    __shared__ __align__(16) float sy [G * LATENT];
    __shared__ __align__(16) float syt[G * LATENT];
    __shared__ __align__(16) float syc[G * GIN];
    __shared__ __align__(16) float shh0[G * NUNITS];
    __shared__ __align__(16) float shh1[G * NUNITS];
    __shared__ __align__(16) float shh2[G * NUNITS];
    __shared__ __align__(16) float spart[3][G][256];   // cross-half gemv partials
    __shared__ __align__(16) float sdec[4][G][128];    // decoder quarter partials
    __shared__ float sdt[G], sdecay[G], smask[G];
    __shared__ float sred[8][G];

    const int tid  = threadIdx.x;
    const int j    = tid & 255;          // output unit for 256-wide gemvs
    const int half = tid >> 8;           // k-half
    const int lane = tid & 31, warp = tid >> 5;
    const int tb   = blockIdx.x * G;

    const ulonglong2* WP = g_wp;

    float* out_prev = out;
    float* out_vol  = out + (size_t)NTRAJ * LATENT;
    float* out_dts  = out + (size_t)NTRAJ * LATENT + (size_t)NTRAJ * NSTEP * DEC_OUT;

    for (int i = tid; i < G * LATENT; i += THREADS) { sy[i] = 0.f; syt[i] = 0.f; }

    for (int t = 0; t < NTP; t++) {
        __syncthreads();

        // ---- setup: xh -> syc tail, mask, dt ----
        {
            int g = tid >> 7, jj = tid & 127;
            syc[g * GIN + LATENT + jj] =
                data[((size_t)(tb + g) * NTP + t) * (2 * INPUT) + jj];
        }
        if (warp < G) {
            const float* xp = data + ((size_t)(tb + warp) * NTP + t) * (2 * INPUT) + INPUT;
            float s = xp[lane] + xp[lane + 32] + xp[lane + 64] + xp[lane + 96];
#pragma unroll
            for (int off = 16; off; off >>= 1) s += __shfl_xor_sync(0xffffffffu, s, off);
            if (lane == 0) smask[warp] = (s > 0.f) ? 1.f : 0.f;
        }
        if (tid < G && t > 0) {
            float d = ts[(size_t)(tb + tid) * NTP + t] - ts[(size_t)(tb + tid) * NTP + t - 1];
            sdt[tid] = d;
            out_dts[(size_t)(tb + tid) * NSTEP + (t - 1)] = d;
        }
        __syncthreads();

        if (t > 0) {
            // ---- decay layer1 (256->256), split-K x2 ----
            {
                const ulonglong2* Wd[1] = { WP + OFF_DK1 + half * 32 * 256 };
                float p[1][G];
                gemv_part<64, 1, 256, 2>(p, Wd, sy + half * 128, LATENT, j);
                if (half) {
#pragma unroll
                    for (int g = 0; g < G; g++) spart[0][g][j] = p[0][g];
                }
                __syncthreads();
                if (!half) {
#pragma unroll
                    for (int g = 0; g < G; g++)
                        shh0[g * NUNITS + j] = fmaxf(p[0][g] + spart[0][g][j] + dk_b1[j], 0.f);
                }
                __syncthreads();
            }
            // ---- decay layer2: 256 -> 1 (half 0 warps) ----
            if (!half) {
                float v[G];
                float w2v = dk_w2[j];
#pragma unroll
                for (int g = 0; g < G; g++) v[g] = shh0[g * NUNITS + j] * w2v;
#pragma unroll
                for (int off = 16; off; off >>= 1)
#pragma unroll
                    for (int g = 0; g < G; g++) v[g] += __shfl_xor_sync(0xffffffffu, v[g], off);
                if (lane == 0)
#pragma unroll
                    for (int g = 0; g < G; g++) sred[warp][g] = v[g];
            }
            __syncthreads();
            if (tid < G) {
                float s = dk_b2[0];
#pragma unroll
                for (int w = 0; w < 8; w++) s += sred[w][tid];
                sdecay[tid] = fmaxf(s, 0.f);
            }
            __syncthreads();

            // ---- elementwise decay: mean_ydec -> shh0, y_end -> sy & syc head ----
            if (!half) {
#pragma unroll
                for (int g = 0; g < G; g++) {
                    float d  = sdecay[g] * sdt[g];
                    float e1 = __expf(-0.5f * d);
                    float e2 = __expf(-d);
                    float yv = sy[g * LATENT + j], ytv = syt[g * LATENT + j];
                    float df = yv - ytv;
                    shh0[g * NUNITS + j] = ytv + df * (0.5f * (1.f + e1));
                    float yend = ytv + df * e2;
                    sy[g * LATENT + j] = yend;
                    syc[g * GIN + j]   = yend;
                }
            }
        } else {
            if (!half) {
#pragma unroll
                for (int g = 0; g < G; g++) syc[g * GIN + j] = 0.f;
            }
        }
        __syncthreads();

        // ==== MERGED SEGMENT: vol decoder + fused gate layer1 (independent) ====
        if (t > 0) {
            // decoder partial (256->128), split-K x4
            int q = tid >> 7, jd = tid & 127;
            const ulonglong2* Wd[1] = { WP + OFF_DEC + q * 16 * 128 };
            float pd[1][G];
            gemv_part<32, 1, 128, 2>(pd, Wd, shh0 + q * 64, NUNITS, jd);
#pragma unroll
            for (int g = 0; g < G; g++) sdec[q][g][jd] = pd[0][g];
        }
        {
            // fused gate layer1: ug/ugt/rg (384->256 x3), shared input syc
            const ulonglong2* Wg[3] = { WP + OFF_UG1  + half * 48 * 256,
                                        WP + OFF_UGT1 + half * 48 * 256,
                                        WP + OFF_RG1  + half * 48 * 256 };
            float p[3][G];
            gemv_part<96, 3, 256, 1>(p, Wg, syc + half * 192, GIN, j);
            if (half) {
#pragma unroll
                for (int ng = 0; ng < 3; ng++)
#pragma unroll
                    for (int g = 0; g < G; g++) spart[ng][g][j] = p[ng][g];
            }
            __syncthreads();
            if (!half) {
#pragma unroll
                for (int g = 0; g < G; g++) {
                    shh0[g * NUNITS + j] = tanhf(p[0][g] + spart[0][g][j] + ug_b1[j]);
                    shh1[g * NUNITS + j] = tanhf(p[1][g] + spart[1][g][j] + ugt_b1[j]);
                    shh2[g * NUNITS + j] = tanhf(p[2][g] + spart[2][g][j] + rg_b1[j]);
                }
            } else if (t > 0 && tid >= 384) {
                // decoder combine + store, on otherwise-idle half-1 warps
                int jd = tid & 127;
                float bv = dec_b[jd];
#pragma unroll
                for (int g = 0; g < G; g++) {
                    float v = sdec[0][g][jd] + sdec[1][g][jd]
                            + sdec[2][g][jd] + sdec[3][g][jd] + bv;
                    out_vol[((size_t)(tb + g) * NSTEP + (t - 1)) * DEC_OUT + jd] = v;
                }
            }
            __syncthreads();
        }

        // ---- gate layer2 x3 (256->256), interleaved NG=3 with per-ng acts ----
        float u[G], ut[G];
        {
            const ulonglong2* Wg[3] = { WP + OFF_UG2  + half * 32 * 256,
                                        WP + OFF_UGT2 + half * 32 * 256,
                                        WP + OFF_RG2  + half * 32 * 256 };
            const float* av[3] = { shh0 + half * 128, shh1 + half * 128, shh2 + half * 128 };
            float p[3][G];
            gemv_part_ma<64, 3, 256>(p, Wg, av, NUNITS, j);
            if (half) {
#pragma unroll
                for (int ng = 0; ng < 3; ng++)
#pragma unroll
                    for (int g = 0; g < G; g++) spart[ng][g][j] = p[ng][g];
            }
            __syncthreads();
            if (!half) {
#pragma unroll
                for (int g = 0; g < G; g++) {
                    u[g]  = sigmoid_fast(p[0][g] + spart[0][g][j] + ug_b2[j]);
                    ut[g] = sigmoid_fast(p[1][g] + spart[1][g][j] + ugt_b2[j]);
                    syc[g * GIN + j] *= sigmoid_fast(p[2][g] + spart[2][g][j] + rg_b2[j]);
                }
            }
            __syncthreads();
        }

        // ---- new_state layer1 (384->256) ----
        {
            const ulonglong2* Wg[1] = { WP + OFF_NS1 + half * 48 * 256 };
            float p[1][G];
            gemv_part<96, 1, 256, 2>(p, Wg, syc + half * 192, GIN, j);
            if (half) {
#pragma unroll
                for (int g = 0; g < G; g++) spart[0][g][j] = p[0][g];
            }
            __syncthreads();
            if (!half) {
#pragma unroll
                for (int g = 0; g < G; g++)
                    shh0[g * NUNITS + j] = tanhf(p[0][g] + spart[0][g][j] + ns_b1[j]);
            }
            __syncthreads();
        }

        // ---- new_state layer2 (256->256) + masked state update ----
        {
            const ulonglong2* Wg[1] = { WP + OFF_NS2 + half * 32 * 256 };
            float p[1][G];
            gemv_part<64, 1, 256, 2>(p, Wg, shh0 + half * 128, NUNITS, j);
            if (half) {
#pragma unroll
                for (int g = 0; g < G; g++) spart[0][g][j] = p[0][g];
            }
            __syncthreads();
            if (!half) {
#pragma unroll
                for (int g = 0; g < G; g++) {
                    float nsv  = p[0][g] + spart[0][g][j] + ns_b2[j];
                    float m    = smask[g];
                    float yend = sy[g * LATENT + j], ytv = syt[g * LATENT + j];
                    float ny   = (1.f - u[g])  * nsv + u[g]  * yend;
                    float nyt  = (1.f - ut[g]) * nsv + ut[g] * ytv;
                    sy [g * LATENT + j] = m * ny  + (1.f - m) * yend;
                    syt[g * LATENT + j] = m * nyt + (1.f - m) * ytv;
                }
            }
        }
        // top-of-loop sync protects sy/syt writes
    }

    __syncthreads();
    if (!half) {
#pragma unroll
        for (int g = 0; g < G; g++)
            out_prev[(size_t)(tb + g) * LATENT + j] = sy[g * LATENT + j];
    }
}

extern "C" void kernel_launch(void* const* d_in, const int* in_sizes, int n_in,
                              void* d_out, int out_size) {
    const float* data   = (const float*)d_in[0];
    const float* ts     = (const float*)d_in[1];
    const float* ug_w1  = (const float*)d_in[2];
    const float* ug_b1  = (const float*)d_in[3];
    const float* ug_w2  = (const float*)d_in[4];
    const float* ug_b2  = (const float*)d_in[5];
    const float* ugt_w1 = (const float*)d_in[6];
    const float* ugt_b1 = (const float*)d_in[7];
    const float* ugt_w2 = (const float*)d_in[8];
    const float* ugt_b2 = (const float*)d_in[9];
    const float* rg_w1  = (const float*)d_in[10];
    const float* rg_b1  = (const float*)d_in[11];
    const float* rg_w2  = (const float*)d_in[12];
    const float* rg_b2  = (const float*)d_in[13];
    // d_in[14..17] = rgt_* : unused by the reference
    const float* ns_w1  = (const float*)d_in[18];
    const float* ns_b1  = (const float*)d_in[19];
    const float* ns_w2  = (const float*)d_in[20];
    const float* ns_b2  = (const float*)d_in[21];
    const float* dk_w1  = (const float*)d_in[22];
    const float* dk_b1  = (const float*)d_in[23];
    const float* dk_w2  = (const float*)d_in[24];
    const float* dk_b2  = (const float*)d_in[25];
    const float* dec_w  = (const float*)d_in[26];
    const float* dec_b  = (const float*)d_in[27];

    pack_kernel<<<(WP_TOTAL + 255) / 256, 256>>>(
        ug_w1, ugt_w1, rg_w1, ns_w1, ug_w2, ugt_w2, rg_w2, ns_w2, dk_w1, dec_w);

    rnn_decay_kernel<<<NBLK, THREADS>>>(
        data, ts,
        ug_b1, ug_b2, ugt_b1, ugt_b2, rg_b1, rg_b2,
        ns_b1, ns_b2, dk_b1, dk_w2, dk_b2, dec_b,
        (float*)d_out);
}

// round 7
// speedup vs baseline: 2.0692x; 1.3378x over previous
#include <cuda_runtime.h>
#include <cuda_bf16.h>
#include <math.h>
#include <stdint.h>
#include <stddef.h>

#define NTRAJ  256
#define NTP    512
#define LATENT 256
#define INPUT  128
#define NUNITS 256
#define GIN    (LATENT + INPUT)   // 384
#define DEC_OUT 128
#define NSTEP  (NTP - 1)          // 511

#define G       4                 // trajectories per cluster
#define NCLU    (NTRAJ / G)       // 64 clusters
#define NBLK    (NCLU * 2)        // 128 CTAs (2 per cluster, K-split)
#define THREADS 256

typedef unsigned long long u64;

union F2U { float2 f; u64 u; };

__device__ __forceinline__ u64 ffma2(u64 a, u64 b, u64 c) {
    u64 d;
    asm("fma.rn.f32x2 %0, %1, %2, %3;" : "=l"(d) : "l"(a), "l"(b), "l"(c));
    return d;
}
__device__ __forceinline__ float lanesum(u64 v) {
    F2U r; r.u = v; return r.f.x + r.f.y;
}
__device__ __forceinline__ float sigmoid_fast(float x) {
    return __fdividef(1.f, 1.f + __expf(-x));
}
__device__ __forceinline__ uint32_t smem_u32(const void* p) {
    uint32_t a;
    asm("{ .reg .u64 t; cvta.to.shared.u64 t, %1; cvt.u32.u64 %0, t; }" : "=r"(a) : "l"(p));
    return a;
}
__device__ __forceinline__ uint32_t ctarank() {
    uint32_t r; asm("mov.u32 %0, %%cluster_ctarank;" : "=r"(r)); return r;
}
__device__ __forceinline__ uint32_t mapa_u32(uint32_t addr, uint32_t rank) {
    uint32_t r;
    asm("mapa.shared::cluster.u32 %0, %1, %2;" : "=r"(r) : "r"(addr), "r"(rank));
    return r;
}
__device__ __forceinline__ void st_peer_f4(uint32_t dst, float a, float b, float c, float d) {
    F2U lo, hi; lo.f = make_float2(a, b); hi.f = make_float2(c, d);
    asm volatile("st.shared::cluster.u64 [%0], %1;" :: "r"(dst),     "l"(lo.u) : "memory");
    asm volatile("st.shared::cluster.u64 [%0], %1;" :: "r"(dst + 8), "l"(hi.u) : "memory");
}
__device__ __forceinline__ void st_peer_f2(uint32_t dst, float a, float b) {
    F2U lo; lo.f = make_float2(a, b);
    asm volatile("st.shared::cluster.u64 [%0], %1;" :: "r"(dst), "l"(lo.u) : "memory");
}
#define CLUSTER_SYNC() do { \
    asm volatile("barrier.cluster.arrive.aligned;" ::: "memory"); \
    asm volatile("barrier.cluster.wait.aligned;"   ::: "memory"); \
} while (0)

// ---------------------------------------------------------------------------
// Packed weights: float4 along k: W4[k4][j] = W[4k4..4k4+3][j], as ulonglong2.
// ---------------------------------------------------------------------------
#define SZ_M384 (96 * 256)
#define SZ_M256 (64 * 256)
#define SZ_DEC  (64 * 128)
#define OFF_UG1  0
#define OFF_UGT1 (OFF_UG1  + SZ_M384)
#define OFF_RG1  (OFF_UGT1 + SZ_M384)
#define OFF_NS1  (OFF_RG1  + SZ_M384)
#define OFF_UG2  (OFF_NS1  + SZ_M384)
#define OFF_UGT2 (OFF_UG2  + SZ_M256)
#define OFF_RG2  (OFF_UGT2 + SZ_M256)
#define OFF_NS2  (OFF_RG2  + SZ_M256)
#define OFF_DK1  (OFF_NS2  + SZ_M256)
#define OFF_DEC  (OFF_DK1  + SZ_M256)
#define WP_TOTAL (OFF_DEC  + SZ_DEC)

__device__ ulonglong2 g_wp[WP_TOTAL];

__global__ void pack_kernel(
    const float* ug1, const float* ugt1, const float* rg1, const float* ns1,
    const float* ug2, const float* ugt2, const float* rg2, const float* ns2,
    const float* dk1, const float* decw)
{
    const float* srcs[10] = {ug1, ugt1, rg1, ns1, ug2, ugt2, rg2, ns2, dk1, decw};
    const int offs[11] = {OFF_UG1, OFF_UGT1, OFF_RG1, OFF_NS1, OFF_UG2, OFF_UGT2,
                          OFF_RG2, OFF_NS2, OFF_DK1, OFF_DEC, WP_TOTAL};
    const int Ns[10] = {256,256,256,256,256,256,256,256,256,128};

    int idx = blockIdx.x * blockDim.x + threadIdx.x;
    if (idx >= WP_TOTAL) return;
    int m = 0;
    while (idx >= offs[m + 1]) m++;
    int local = idx - offs[m];
    int N = Ns[m];
    int k4 = local / N, j = local % N;
    const float* S = srcs[m];
    F2U lo, hi;
    lo.f = make_float2(S[(4 * k4 + 0) * N + j], S[(4 * k4 + 1) * N + j]);
    hi.f = make_float2(S[(4 * k4 + 2) * N + j], S[(4 * k4 + 3) * N + j]);
    g_wp[idx] = make_ulonglong2(lo.u, hi.u);
}

// ---------------------------------------------------------------------------
// Partial packed GEMV, shared activation input. A/B register double-buffer.
// ---------------------------------------------------------------------------
template <int K2H, int NG, int N, int CU>
__device__ __forceinline__ void gemv_part(
    float (&res)[NG][G],
    const ulonglong2* const (&Wv)[NG],
    const float* act, int astride, int j)
{
    constexpr int K4 = K2H / 2;
    constexpr int CH = K4 / CU;
    static_assert(CH % 2 == 0, "chunks must be even");

    u64 acc[NG][G];
#pragma unroll
    for (int ng = 0; ng < NG; ng++)
#pragma unroll
        for (int g = 0; g < G; g++) acc[ng][g] = 0ull;

    ulonglong2 wA[NG][CU], wB[NG][CU];

    auto LD = [&](ulonglong2 (&w)[NG][CU], int c) {
#pragma unroll
        for (int ng = 0; ng < NG; ng++)
#pragma unroll
            for (int cu = 0; cu < CU; cu++)
                w[ng][cu] = Wv[ng][(c * CU + cu) * N + j];
    };
    auto CP = [&](ulonglong2 (&w)[NG][CU], int c) {
#pragma unroll
        for (int cu = 0; cu < CU; cu++) {
            int k4 = c * CU + cu;
            u64 a0[G], a1[G];
#pragma unroll
            for (int g = 0; g < G; g++) {
                ulonglong2 av = *(const ulonglong2*)(act + g * astride + 4 * k4);
                a0[g] = av.x; a1[g] = av.y;
            }
#pragma unroll
            for (int ng = 0; ng < NG; ng++)
#pragma unroll
                for (int g = 0; g < G; g++) {
                    acc[ng][g] = ffma2(a0[g], w[ng][cu].x, acc[ng][g]);
                    acc[ng][g] = ffma2(a1[g], w[ng][cu].y, acc[ng][g]);
                }
        }
    };

    LD(wA, 0);
#pragma unroll 1
    for (int cc = 0; cc < CH / 2; cc++) {
        LD(wB, 2 * cc + 1);
        CP(wA, 2 * cc);
        if (cc + 1 < CH / 2) LD(wA, 2 * cc + 2);
        CP(wB, 2 * cc + 1);
    }

#pragma unroll
    for (int ng = 0; ng < NG; ng++)
#pragma unroll
        for (int g = 0; g < G; g++) res[ng][g] = lanesum(acc[ng][g]);
}

// Per-matrix activation variant (gate layer 2).
template <int K2H, int NG, int N>
__device__ __forceinline__ void gemv_part_ma(
    float (&res)[NG][G],
    const ulonglong2* const (&Wv)[NG],
    const float* const (&av)[NG], int astride, int j)
{
    constexpr int CH = K2H / 2;
    static_assert(CH % 2 == 0, "chunks must be even");

    u64 acc[NG][G];
#pragma unroll
    for (int ng = 0; ng < NG; ng++)
#pragma unroll
        for (int g = 0; g < G; g++) acc[ng][g] = 0ull;

    ulonglong2 wA[NG], wB[NG];

    auto LD = [&](ulonglong2 (&w)[NG], int c) {
#pragma unroll
        for (int ng = 0; ng < NG; ng++) w[ng] = Wv[ng][c * N + j];
    };
    auto CP = [&](ulonglong2 (&w)[NG], int c) {
#pragma unroll
        for (int ng = 0; ng < NG; ng++) {
#pragma unroll
            for (int g = 0; g < G; g++) {
                ulonglong2 avv = *(const ulonglong2*)(av[ng] + g * astride + 4 * c);
                acc[ng][g] = ffma2(avv.x, w[ng].x, acc[ng][g]);
                acc[ng][g] = ffma2(avv.y, w[ng].y, acc[ng][g]);
            }
        }
    };

    LD(wA, 0);
#pragma unroll 1
    for (int cc = 0; cc < CH / 2; cc++) {
        LD(wB, 2 * cc + 1);
        CP(wA, 2 * cc);
        if (cc + 1 < CH / 2) LD(wA, 2 * cc + 2);
        CP(wB, 2 * cc + 1);
    }

#pragma unroll
    for (int ng = 0; ng < NG; ng++)
#pragma unroll
        for (int g = 0; g < G; g++) res[ng][g] = lanesum(acc[ng][g]);
}

// Decoder partial: 2 trajectories, K4=32 rows of this rank's half, N=128.
__device__ __forceinline__ void gemv_dec2(
    float (&res)[2], const ulonglong2* W,
    const float* act0, const float* act1, int jd)
{
    constexpr int CU = 4, CH = 8;  // 32 k4 rows
    u64 acc0 = 0ull, acc1 = 0ull;
    ulonglong2 wA[CU], wB[CU];

    auto LD = [&](ulonglong2 (&w)[CU], int c) {
#pragma unroll
        for (int cu = 0; cu < CU; cu++) w[cu] = W[(c * CU + cu) * 128 + jd];
    };
    auto CP = [&](ulonglong2 (&w)[CU], int c) {
#pragma unroll
        for (int cu = 0; cu < CU; cu++) {
            int k4 = c * CU + cu;
            ulonglong2 a0 = *(const ulonglong2*)(act0 + 4 * k4);
            ulonglong2 a1 = *(const ulonglong2*)(act1 + 4 * k4);
            acc0 = ffma2(a0.x, w[cu].x, acc0);
            acc0 = ffma2(a0.y, w[cu].y, acc0);
            acc1 = ffma2(a1.x, w[cu].x, acc1);
            acc1 = ffma2(a1.y, w[cu].y, acc1);
        }
    };

    LD(wA, 0);
#pragma unroll 1
    for (int cc = 0; cc < CH / 2; cc++) {
        LD(wB, 2 * cc + 1);
        CP(wA, 2 * cc);
        if (cc + 1 < CH / 2) LD(wA, 2 * cc + 2);
        CP(wB, 2 * cc + 1);
    }
    res[0] = lanesum(acc0);
    res[1] = lanesum(acc1);
}

// ---------------------------------------------------------------------------
// Shared memory layout (dynamic).
// ---------------------------------------------------------------------------
struct __align__(16) SM {
    float sy  [G * LATENT];     // y state (y_end after decay)
    float syc [G * GIN];        // [y*r | xh]
    float shh0[G * NUNITS];
    float shh1[G * NUNITS];
    float shh2[G * NUNITS];
    float A[3][256][G];         // exchange set A (peer writes)
    float B[3][256][G];         // exchange set B (peer writes)
    float D[128][G];            // decoder partial from rank1 (rank0 reads)
    float sdt[G], sdecay[G], smask[G];
    float sred[8][G];
};
#define SMEM_BYTES ((int)sizeof(SM))

__global__ void __cluster_dims__(2, 1, 1) __launch_bounds__(THREADS, 1)
rnn_decay_kernel(
    const float* __restrict__ data, const float* __restrict__ ts,
    const float* __restrict__ ug_b1,  const float* __restrict__ ug_b2,
    const float* __restrict__ ugt_b1, const float* __restrict__ ugt_b2,
    const float* __restrict__ rg_b1,  const float* __restrict__ rg_b2,
    const float* __restrict__ ns_b1,  const float* __restrict__ ns_b2,
    const float* __restrict__ dk_b1,  const float* __restrict__ dk_w2,
    const float* __restrict__ dk_b2,  const float* __restrict__ dec_b,
    float* __restrict__ out)
{
    extern __shared__ __align__(16) char smraw[];
    SM* sm = reinterpret_cast<SM*>(smraw);

    const int tid  = threadIdx.x;       // 0..255, one output unit j = tid
    const int j    = tid;
    const int lane = tid & 31, warp = tid >> 5;
    const uint32_t rank = ctarank();    // k-half owned by this CTA
    const int tb   = (blockIdx.x >> 1) * G;

    const uint32_t sb = smem_u32(sm);
    const uint32_t pb = mapa_u32(sb, rank ^ 1u);
    const uint32_t pA = pb + (uint32_t)offsetof(SM, A);
    const uint32_t pB = pb + (uint32_t)offsetof(SM, B);
    const uint32_t pD = pb + (uint32_t)offsetof(SM, D);

    const ulonglong2* WP = g_wp;

    float* out_prev = out;
    float* out_vol  = out + (size_t)NTRAJ * LATENT;
    float* out_dts  = out + (size_t)NTRAJ * LATENT + (size_t)NTRAJ * NSTEP * DEC_OUT;

    float yt[G];
#pragma unroll
    for (int g = 0; g < G; g++) {
        yt[g] = 0.f;
        sm->sy[g * LATENT + j] = 0.f;
    }

    // decoder thread mapping
    const int jd = tid & 127, h2 = tid >> 7;     // h2 selects trajectory pair

    for (int t = 0; t < NTP; t++) {
        CLUSTER_SYNC();   // S0: aligns steps; protects sy/syc & buffer reuse

        // ---- setup: xh -> syc tail, mask, dt (redundant in both ranks) ----
        for (int i = tid; i < G * INPUT; i += THREADS) {
            int g = i >> 7, jj = i & 127;
            sm->syc[g * GIN + LATENT + jj] =
                data[((size_t)(tb + g) * NTP + t) * (2 * INPUT) + jj];
        }
        if (warp < G) {
            const float* xp = data + ((size_t)(tb + warp) * NTP + t) * (2 * INPUT) + INPUT;
            float s = xp[lane] + xp[lane + 32] + xp[lane + 64] + xp[lane + 96];
#pragma unroll
            for (int off = 16; off; off >>= 1) s += __shfl_xor_sync(0xffffffffu, s, off);
            if (lane == 0) sm->smask[warp] = (s > 0.f) ? 1.f : 0.f;
        }
        if (tid < G && t > 0) {
            float d = ts[(size_t)(tb + tid) * NTP + t] - ts[(size_t)(tb + tid) * NTP + t - 1];
            sm->sdt[tid] = d;
            if (rank == 0)
                out_dts[(size_t)(tb + tid) * NSTEP + (t - 1)] = d;
        }
        __syncthreads();

        float pdec[2];  // decoder own-half partial (used by both ranks)

        if (t > 0) {
            // ---- decay layer1 (256->256), K-split across ranks ----
            {
                const ulonglong2* Wd[1] = { WP + OFF_DK1 + rank * 32 * 256 };
                float p[1][G];
                gemv_part<64, 1, 256, 4>(p, Wd, sm->sy + rank * 128, LATENT, j);
                st_peer_f4(pA + (uint32_t)((0 * 256 + j) * G * 4),
                           p[0][0], p[0][1], p[0][2], p[0][3]);
                CLUSTER_SYNC();  // S1
                float bv = dk_b1[j];
                float4 pr = *(const float4*)&sm->A[0][j][0];
                sm->shh0[0 * NUNITS + j] = fmaxf(p[0][0] + pr.x + bv, 0.f);
                sm->shh0[1 * NUNITS + j] = fmaxf(p[0][1] + pr.y + bv, 0.f);
                sm->shh0[2 * NUNITS + j] = fmaxf(p[0][2] + pr.z + bv, 0.f);
                sm->shh0[3 * NUNITS + j] = fmaxf(p[0][3] + pr.w + bv, 0.f);
            }
            // ---- decay layer2: 256->1 (redundant in both ranks) ----
            {
                float v[G];
                float w2v = dk_w2[j];
#pragma unroll
                for (int g = 0; g < G; g++) v[g] = sm->shh0[g * NUNITS + j] * w2v;
#pragma unroll
                for (int off = 16; off; off >>= 1)
#pragma unroll
                    for (int g = 0; g < G; g++) v[g] += __shfl_xor_sync(0xffffffffu, v[g], off);
                if (lane == 0)
#pragma unroll
                    for (int g = 0; g < G; g++) sm->sred[warp][g] = v[g];
            }
            __syncthreads();
            if (tid < G) {
                float s = dk_b2[0];
#pragma unroll
                for (int w = 0; w < 8; w++) s += sm->sred[w][tid];
                sm->sdecay[tid] = fmaxf(s, 0.f);
            }
            __syncthreads();

            // ---- elementwise decay (all threads, all g) ----
#pragma unroll
            for (int g = 0; g < G; g++) {
                float d  = sm->sdecay[g] * sm->sdt[g];
                float e1 = __expf(-0.5f * d);
                float e2 = __expf(-d);
                float yv = sm->sy[g * LATENT + j], ytv = yt[g];
                float df = yv - ytv;
                sm->shh0[g * NUNITS + j] = ytv + df * (0.5f * (1.f + e1));  // mean_ydec
                float yend = ytv + df * e2;
                sm->sy[g * LATENT + j] = yend;
                sm->syc[g * GIN + j]   = yend;
            }
            __syncthreads();

            // ---- decoder partial (K-half of mean_ydec), g split by h2 ----
            {
                const ulonglong2* Wd = WP + OFF_DEC + rank * 32 * 128;
                int g0 = 2 * h2;
                gemv_dec2(pdec, Wd,
                          sm->shh0 + (g0 + 0) * NUNITS + rank * 128,
                          sm->shh0 + (g0 + 1) * NUNITS + rank * 128, jd);
                if (rank == 1)
                    st_peer_f2(pD + (uint32_t)((jd * G + g0) * 4), pdec[0], pdec[1]);
            }
        } else {
#pragma unroll
            for (int g = 0; g < G; g++) sm->syc[g * GIN + j] = 0.f;
            __syncthreads();
        }

        // ---- fused gate layer1: ug/ugt/rg (384->256 x3), K-split ----
        {
            const ulonglong2* Wg[3] = { WP + OFF_UG1  + rank * 48 * 256,
                                        WP + OFF_UGT1 + rank * 48 * 256,
                                        WP + OFF_RG1  + rank * 48 * 256 };
            float p[3][G];
            gemv_part<96, 3, 256, 1>(p, Wg, sm->syc + rank * 192, GIN, j);
#pragma unroll
            for (int ng = 0; ng < 3; ng++)
                st_peer_f4(pB + (uint32_t)(((ng * 256) + j) * G * 4),
                           p[ng][0], p[ng][1], p[ng][2], p[ng][3]);
            CLUSTER_SYNC();  // S2
            float b0 = ug_b1[j], b1 = ugt_b1[j], b2 = rg_b1[j];
            float4 r0 = *(const float4*)&sm->B[0][j][0];
            float4 r1 = *(const float4*)&sm->B[1][j][0];
            float4 r2 = *(const float4*)&sm->B[2][j][0];
            sm->shh0[0 * NUNITS + j] = tanhf(p[0][0] + r0.x + b0);
            sm->shh0[1 * NUNITS + j] = tanhf(p[0][1] + r0.y + b0);
            sm->shh0[2 * NUNITS + j] = tanhf(p[0][2] + r0.z + b0);
            sm->shh0[3 * NUNITS + j] = tanhf(p[0][3] + r0.w + b0);
            sm->shh1[0 * NUNITS + j] = tanhf(p[1][0] + r1.x + b1);
            sm->shh1[1 * NUNITS + j] = tanhf(p[1][1] + r1.y + b1);
            sm->shh1[2 * NUNITS + j] = tanhf(p[1][2] + r1.z + b1);
            sm->shh1[3 * NUNITS + j] = tanhf(p[1][3] + r1.w + b1);
            sm->shh2[0 * NUNITS + j] = tanhf(p[2][0] + r2.x + b2);
            sm->shh2[1 * NUNITS + j] = tanhf(p[2][1] + r2.y + b2);
            sm->shh2[2 * NUNITS + j] = tanhf(p[2][2] + r2.z + b2);
            sm->shh2[3 * NUNITS + j] = tanhf(p[2][3] + r2.w + b2);

            // decoder finalize on rank0 (own half in regs + peer half in D)
            if (t > 0 && rank == 0) {
                int g0 = 2 * h2;
                float bv = dec_b[jd];
                float v0 = pdec[0] + sm->D[jd][g0 + 0] + bv;
                float v1 = pdec[1] + sm->D[jd][g0 + 1] + bv;
                out_vol[((size_t)(tb + g0 + 0) * NSTEP + (t - 1)) * DEC_OUT + jd] = v0;
                out_vol[((size_t)(tb + g0 + 1) * NSTEP + (t - 1)) * DEC_OUT + jd] = v1;
            }
            __syncthreads();
        }

        // ---- gate layer2 x3 (256->256), per-matrix acts, K-split ----
        float u[G], ut[G];
        {
            const ulonglong2* Wg[3] = { WP + OFF_UG2  + rank * 32 * 256,
                                        WP + OFF_UGT2 + rank * 32 * 256,
                                        WP + OFF_RG2  + rank * 32 * 256 };
            const float* av[3] = { sm->shh0 + rank * 128, sm->shh1 + rank * 128,
                                   sm->shh2 + rank * 128 };
            float p[3][G];
            gemv_part_ma<64, 3, 256>(p, Wg, av, NUNITS, j);
#pragma unroll
            for (int ng = 0; ng < 3; ng++)
                st_peer_f4(pA + (uint32_t)(((ng * 256) + j) * G * 4),
                           p[ng][0], p[ng][1], p[ng][2], p[ng][3]);
            CLUSTER_SYNC();  // S3
            float b0 = ug_b2[j], b1 = ugt_b2[j], b2 = rg_b2[j];
            float4 r0 = *(const float4*)&sm->A[0][j][0];
            float4 r1 = *(const float4*)&sm->A[1][j][0];
            float4 r2 = *(const float4*)&sm->A[2][j][0];
            u[0]  = sigmoid_fast(p[0][0] + r0.x + b0);
            u[1]  = sigmoid_fast(p[0][1] + r0.y + b0);
            u[2]  = sigmoid_fast(p[0][2] + r0.z + b0);
            u[3]  = sigmoid_fast(p[0][3] + r0.w + b0);
            ut[0] = sigmoid_fast(p[1][0] + r1.x + b1);
            ut[1] = sigmoid_fast(p[1][1] + r1.y + b1);
            ut[2] = sigmoid_fast(p[1][2] + r1.z + b1);
            ut[3] = sigmoid_fast(p[1][3] + r1.w + b1);
            sm->syc[0 * GIN + j] *= sigmoid_fast(p[2][0] + r2.x + b2);
            sm->syc[1 * GIN + j] *= sigmoid_fast(p[2][1] + r2.y + b2);
            sm->syc[2 * GIN + j] *= sigmoid_fast(p[2][2] + r2.z + b2);
            sm->syc[3 * GIN + j] *= sigmoid_fast(p[2][3] + r2.w + b2);
            __syncthreads();
        }

        // ---- new_state layer1 (384->256), K-split ----
        {
            const ulonglong2* Wg[1] = { WP + OFF_NS1 + rank * 48 * 256 };
            float p[1][G];
            gemv_part<96, 1, 256, 4>(p, Wg, sm->syc + rank * 192, GIN, j);
            st_peer_f4(pB + (uint32_t)((0 * 256 + j) * G * 4),
                       p[0][0], p[0][1], p[0][2], p[0][3]);
            CLUSTER_SYNC();  // S4
            float bv = ns_b1[j];
            float4 pr = *(const float4*)&sm->B[0][j][0];
            sm->shh0[0 * NUNITS + j] = tanhf(p[0][0] + pr.x + bv);
            sm->shh0[1 * NUNITS + j] = tanhf(p[0][1] + pr.y + bv);
            sm->shh0[2 * NUNITS + j] = tanhf(p[0][2] + pr.z + bv);
            sm->shh0[3 * NUNITS + j] = tanhf(p[0][3] + pr.w + bv);
            __syncthreads();
        }

        // ---- new_state layer2 (256->256) + masked update ----
        {
            const ulonglong2* Wg[1] = { WP + OFF_NS2 + rank * 32 * 256 };
            float p[1][G];
            gemv_part<64, 1, 256, 4>(p, Wg, sm->shh0 + rank * 128, NUNITS, j);
            st_peer_f4(pA + (uint32_t)((0 * 256 + j) * G * 4),
                       p[0][0], p[0][1], p[0][2], p[0][3]);
            CLUSTER_SYNC();  // S5
            float bv = ns_b2[j];
            float4 pr = *(const float4*)&sm->A[0][j][0];
            float prv[G] = { pr.x, pr.y, pr.z, pr.w };
#pragma unroll
            for (int g = 0; g < G; g++) {
                float nsv  = p[0][g] + prv[g] + bv;
                float m    = sm->smask[g];
                float yend = sm->sy[g * LATENT + j], ytv = yt[g];
                float ny   = (1.f - u[g])  * nsv + u[g]  * yend;
                float nyt  = (1.f - ut[g]) * nsv + ut[g] * ytv;
                sm->sy[g * LATENT + j] = m * ny  + (1.f - m) * yend;
                yt[g]                  = m * nyt + (1.f - m) * ytv;
            }
        }
        // S0 of next iteration protects sy writes & exchange-buffer reuse
    }

    CLUSTER_SYNC();
    if (rank == 0) {
#pragma unroll
        for (int g = 0; g < G; g++)
            out_prev[(size_t)(tb + g) * LATENT + j] = sm->sy[g * LATENT + j];
    }
}

extern "C" void kernel_launch(void* const* d_in, const int* in_sizes, int n_in,
                              void* d_out, int out_size) {
    const float* data   = (const float*)d_in[0];
    const float* ts     = (const float*)d_in[1];
    const float* ug_w1  = (const float*)d_in[2];
    const float* ug_b1  = (const float*)d_in[3];
    const float* ug_w2  = (const float*)d_in[4];
    const float* ug_b2  = (const float*)d_in[5];
    const float* ugt_w1 = (const float*)d_in[6];
    const float* ugt_b1 = (const float*)d_in[7];
    const float* ugt_w2 = (const float*)d_in[8];
    const float* ugt_b2 = (const float*)d_in[9];
    const float* rg_w1  = (const float*)d_in[10];
    const float* rg_b1  = (const float*)d_in[11];
    const float* rg_w2  = (const float*)d_in[12];
    const float* rg_b2  = (const float*)d_in[13];
    // d_in[14..17] = rgt_* : unused by the reference
    const float* ns_w1  = (const float*)d_in[18];
    const float* ns_b1  = (const float*)d_in[19];
    const float* ns_w2  = (const float*)d_in[20];
    const float* ns_b2  = (const float*)d_in[21];
    const float* dk_w1  = (const float*)d_in[22];
    const float* dk_b1  = (const float*)d_in[23];
    const float* dk_w2  = (const float*)d_in[24];
    const float* dk_b2  = (const float*)d_in[25];
    const float* dec_w  = (const float*)d_in[26];
    const float* dec_b  = (const float*)d_in[27];

    cudaFuncSetAttribute(rnn_decay_kernel,
                         cudaFuncAttributeMaxDynamicSharedMemorySize, SMEM_BYTES);

    pack_kernel<<<(WP_TOTAL + 255) / 256, 256>>>(
        ug_w1, ugt_w1, rg_w1, ns_w1, ug_w2, ugt_w2, rg_w2, ns_w2, dk_w1, dec_w);

    rnn_decay_kernel<<<NBLK, THREADS, SMEM_BYTES>>>(
        data, ts,
        ug_b1, ug_b2, ugt_b1, ugt_b2, rg_b1, rg_b2,
        ns_b1, ns_b2, dk_b1, dk_w2, dk_b2, dec_b,
        (float*)d_out);
}

// round 9
// speedup vs baseline: 2.1684x; 1.0479x over previous
#include <cuda_runtime.h>
#include <cuda_bf16.h>
#include <math.h>
#include <stdint.h>
#include <stddef.h>

#define NTRAJ  256
#define NTP    512
#define LATENT 256
#define INPUT  128
#define NUNITS 256
#define GIN    (LATENT + INPUT)   // 384
#define DEC_OUT 128
#define NSTEP  (NTP - 1)          // 511

#define G       4                 // trajectories per cluster
#define NCLU    (NTRAJ / G)       // 64 clusters
#define NBLK    (NCLU * 2)        // 128 CTAs (2 per cluster, K-split)
#define THREADS 512               // intra-CTA split-K x2 on top of cluster split

typedef unsigned long long u64;

union F2U { float2 f; u64 u; };

__device__ __forceinline__ u64 ffma2(u64 a, u64 b, u64 c) {
    u64 d;
    asm("fma.rn.f32x2 %0, %1, %2, %3;" : "=l"(d) : "l"(a), "l"(b), "l"(c));
    return d;
}
__device__ __forceinline__ float lanesum(u64 v) {
    F2U r; r.u = v; return r.f.x + r.f.y;
}
__device__ __forceinline__ float sigmoid_fast(float x) {
    return __fdividef(1.f, 1.f + __expf(-x));
}
__device__ __forceinline__ uint32_t smem_u32(const void* p) {
    uint32_t a;
    asm("{ .reg .u64 t; cvta.to.shared.u64 t, %1; cvt.u32.u64 %0, t; }" : "=r"(a) : "l"(p));
    return a;
}
__device__ __forceinline__ uint32_t ctarank() {
    uint32_t r; asm("mov.u32 %0, %%cluster_ctarank;" : "=r"(r)); return r;
}
__device__ __forceinline__ uint32_t mapa_u32(uint32_t addr, uint32_t rank) {
    uint32_t r;
    asm("mapa.shared::cluster.u32 %0, %1, %2;" : "=r"(r) : "r"(addr), "r"(rank));
    return r;
}
__device__ __forceinline__ void st_peer_f4(uint32_t dst, float a, float b, float c, float d) {
    F2U lo, hi; lo.f = make_float2(a, b); hi.f = make_float2(c, d);
    asm volatile("st.shared::cluster.u64 [%0], %1;" :: "r"(dst),     "l"(lo.u) : "memory");
    asm volatile("st.shared::cluster.u64 [%0], %1;" :: "r"(dst + 8), "l"(hi.u) : "memory");
}
__device__ __forceinline__ void st_peer_f2(uint32_t dst, float a, float b) {
    F2U lo; lo.f = make_float2(a, b);
    asm volatile("st.shared::cluster.u64 [%0], %1;" :: "r"(dst), "l"(lo.u) : "memory");
}
#define CLUSTER_SYNC() do { \
    asm volatile("barrier.cluster.arrive.aligned;" ::: "memory"); \
    asm volatile("barrier.cluster.wait.aligned;"   ::: "memory"); \
} while (0)

// ---------------------------------------------------------------------------
// Packed weights: float4 along k: W4[k4][j] = W[4k4..4k4+3][j], as ulonglong2.
// ---------------------------------------------------------------------------
#define SZ_M384 (96 * 256)
#define SZ_M256 (64 * 256)
#define SZ_DEC  (64 * 128)
#define OFF_UG1  0
#define OFF_UGT1 (OFF_UG1  + SZ_M384)
#define OFF_RG1  (OFF_UGT1 + SZ_M384)
#define OFF_NS1  (OFF_RG1  + SZ_M384)
#define OFF_UG2  (OFF_NS1  + SZ_M384)
#define OFF_UGT2 (OFF_UG2  + SZ_M256)
#define OFF_RG2  (OFF_UGT2 + SZ_M256)
#define OFF_NS2  (OFF_RG2  + SZ_M256)
#define OFF_DK1  (OFF_NS2  + SZ_M256)
#define OFF_DEC  (OFF_DK1  + SZ_M256)
#define WP_TOTAL (OFF_DEC  + SZ_DEC)

__device__ ulonglong2 g_wp[WP_TOTAL];

__global__ void pack_kernel(
    const float* ug1, const float* ugt1, const float* rg1, const float* ns1,
    const float* ug2, const float* ugt2, const float* rg2, const float* ns2,
    const float* dk1, const float* decw)
{
    const float* srcs[10] = {ug1, ugt1, rg1, ns1, ug2, ugt2, rg2, ns2, dk1, decw};
    const int offs[11] = {OFF_UG1, OFF_UGT1, OFF_RG1, OFF_NS1, OFF_UG2, OFF_UGT2,
                          OFF_RG2, OFF_NS2, OFF_DK1, OFF_DEC, WP_TOTAL};
    const int Ns[10] = {256,256,256,256,256,256,256,256,256,128};

    int idx = blockIdx.x * blockDim.x + threadIdx.x;
    if (idx >= WP_TOTAL) return;
    int m = 0;
    while (idx >= offs[m + 1]) m++;
    int local = idx - offs[m];
    int N = Ns[m];
    int k4 = local / N, j = local % N;
    const float* S = srcs[m];
    F2U lo, hi;
    lo.f = make_float2(S[(4 * k4 + 0) * N + j], S[(4 * k4 + 1) * N + j]);
    hi.f = make_float2(S[(4 * k4 + 2) * N + j], S[(4 * k4 + 3) * N + j]);
    g_wp[idx] = make_ulonglong2(lo.u, hi.u);
}

// ---------------------------------------------------------------------------
// Partial packed GEMV, shared activation input. A/B register double-buffer.
// ---------------------------------------------------------------------------
template <int K2H, int NG, int N, int CU>
__device__ __forceinline__ void gemv_part(
    float (&res)[NG][G],
    const ulonglong2* const (&Wv)[NG],
    const float* act, int astride, int j)
{
    constexpr int K4 = K2H / 2;
    constexpr int CH = K4 / CU;
    static_assert(CH % 2 == 0, "chunks must be even");

    u64 acc[NG][G];
#pragma unroll
    for (int ng = 0; ng < NG; ng++)
#pragma unroll
        for (int g = 0; g < G; g++) acc[ng][g] = 0ull;

    ulonglong2 wA[NG][CU], wB[NG][CU];

    auto LD = [&](ulonglong2 (&w)[NG][CU], int c) {
#pragma unroll
        for (int ng = 0; ng < NG; ng++)
#pragma unroll
            for (int cu = 0; cu < CU; cu++)
                w[ng][cu] = Wv[ng][(c * CU + cu) * N + j];
    };
    auto CP = [&](ulonglong2 (&w)[NG][CU], int c) {
#pragma unroll
        for (int cu = 0; cu < CU; cu++) {
            int k4 = c * CU + cu;
            u64 a0[G], a1[G];
#pragma unroll
            for (int g = 0; g < G; g++) {
                ulonglong2 av = *(const ulonglong2*)(act + g * astride + 4 * k4);
                a0[g] = av.x; a1[g] = av.y;
            }
#pragma unroll
            for (int ng = 0; ng < NG; ng++)
#pragma unroll
                for (int g = 0; g < G; g++) {
                    acc[ng][g] = ffma2(a0[g], w[ng][cu].x, acc[ng][g]);
                    acc[ng][g] = ffma2(a1[g], w[ng][cu].y, acc[ng][g]);
                }
        }
    };

    LD(wA, 0);
#pragma unroll 1
    for (int cc = 0; cc < CH / 2; cc++) {
        LD(wB, 2 * cc + 1);
        CP(wA, 2 * cc);
        if (cc + 1 < CH / 2) LD(wA, 2 * cc + 2);
        CP(wB, 2 * cc + 1);
    }

#pragma unroll
    for (int ng = 0; ng < NG; ng++)
#pragma unroll
        for (int g = 0; g < G; g++) res[ng][g] = lanesum(acc[ng][g]);
}

// Per-matrix activation variant (gate layer 2).
template <int K2H, int NG, int N>
__device__ __forceinline__ void gemv_part_ma(
    float (&res)[NG][G],
    const ulonglong2* const (&Wv)[NG],
    const float* const (&av)[NG], int astride, int j)
{
    constexpr int CH = K2H / 2;
    static_assert(CH % 2 == 0, "chunks must be even");

    u64 acc[NG][G];
#pragma unroll
    for (int ng = 0; ng < NG; ng++)
#pragma unroll
        for (int g = 0; g < G; g++) acc[ng][g] = 0ull;

    ulonglong2 wA[NG], wB[NG];

    auto LD = [&](ulonglong2 (&w)[NG], int c) {
#pragma unroll
        for (int ng = 0; ng < NG; ng++) w[ng] = Wv[ng][c * N + j];
    };
    auto CP = [&](ulonglong2 (&w)[NG], int c) {
#pragma unroll
        for (int ng = 0; ng < NG; ng++) {
#pragma unroll
            for (int g = 0; g < G; g++) {
                ulonglong2 avv = *(const ulonglong2*)(av[ng] + g * astride + 4 * c);
                acc[ng][g] = ffma2(avv.x, w[ng].x, acc[ng][g]);
                acc[ng][g] = ffma2(avv.y, w[ng].y, acc[ng][g]);
            }
        }
    };

    LD(wA, 0);
#pragma unroll 1
    for (int cc = 0; cc < CH / 2; cc++) {
        LD(wB, 2 * cc + 1);
        CP(wA, 2 * cc);
        if (cc + 1 < CH / 2) LD(wA, 2 * cc + 2);
        CP(wB, 2 * cc + 1);
    }

#pragma unroll
    for (int ng = 0; ng < NG; ng++)
#pragma unroll
        for (int g = 0; g < G; g++) res[ng][g] = lanesum(acc[ng][g]);
}

// Decoder partial: 2 trajectories, 16 k4 rows (one K-quarter), N=128.
__device__ __forceinline__ void gemv_dec2(
    float (&res)[2], const ulonglong2* W,
    const float* act0, const float* act1, int jd)
{
    constexpr int CU = 4, CH = 4;  // 16 k4 rows
    u64 acc0 = 0ull, acc1 = 0ull;
    ulonglong2 wA[CU], wB[CU];

    auto LD = [&](ulonglong2 (&w)[CU], int c) {
#pragma unroll
        for (int cu = 0; cu < CU; cu++) w[cu] = W[(c * CU + cu) * 128 + jd];
    };
    auto CP = [&](ulonglong2 (&w)[CU], int c) {
#pragma unroll
        for (int cu = 0; cu < CU; cu++) {
            int k4 = c * CU + cu;
            ulonglong2 a0 = *(const ulonglong2*)(act0 + 4 * k4);
            ulonglong2 a1 = *(const ulonglong2*)(act1 + 4 * k4);
            acc0 = ffma2(a0.x, w[cu].x, acc0);
            acc0 = ffma2(a0.y, w[cu].y, acc0);
            acc1 = ffma2(a1.x, w[cu].x, acc1);
            acc1 = ffma2(a1.y, w[cu].y, acc1);
        }
    };

    LD(wA, 0);
#pragma unroll 1
    for (int cc = 0; cc < CH / 2; cc++) {
        LD(wB, 2 * cc + 1);
        CP(wA, 2 * cc);
        if (cc + 1 < CH / 2) LD(wA, 2 * cc + 2);
        CP(wB, 2 * cc + 1);
    }
    res[0] = lanesum(acc0);
    res[1] = lanesum(acc1);
}

// ---------------------------------------------------------------------------
// Shared memory layout (dynamic).
// ---------------------------------------------------------------------------
struct __align__(16) SM {
    float sy  [G * LATENT];     // y state (y_end after decay)
    float syt [G * LATENT];     // yt state
    float syc [G * GIN];        // [y*r | xh]
    float shh0[G * NUNITS];
    float shh1[G * NUNITS];
    float shh2[G * NUNITS];
    float P[3][256][G];         // intra-CTA quarter partials (q1 writes)
    float A[3][256][G];         // cluster exchange set A (peer writes)
    float B[3][256][G];         // cluster exchange set B (peer writes)
    float D[128][G];            // decoder rank partial (rank1 -> rank0)
    float Pd[128][G];           // decoder intra-CTA partial (kq1 writes)
    float sdt[G], sdecay[G], smask[G];
    float sred[8][G];
};
#define SMEM_BYTES ((int)sizeof(SM))

__global__ void __cluster_dims__(2, 1, 1) __launch_bounds__(THREADS, 1)
rnn_decay_kernel(
    const float* __restrict__ data, const float* __restrict__ ts,
    const float* __restrict__ ug_b1,  const float* __restrict__ ug_b2,
    const float* __restrict__ ugt_b1, const float* __restrict__ ugt_b2,
    const float* __restrict__ rg_b1,  const float* __restrict__ rg_b2,
    const float* __restrict__ ns_b1,  const float* __restrict__ ns_b2,
    const float* __restrict__ dk_b1,  const float* __restrict__ dk_w2,
    const float* __restrict__ dk_b2,  const float* __restrict__ dec_b,
    float* __restrict__ out)
{
    extern __shared__ __align__(16) char smraw[];
    SM* sm = reinterpret_cast<SM*>(smraw);

    const int tid  = threadIdx.x;        // 0..511
    const int j    = tid & 255;          // output unit
    const int q    = tid >> 8;           // intra-CTA k-quarter
    const int lane = tid & 31, warp = tid >> 5;
    const uint32_t rank = ctarank();     // k-half owned by this CTA
    const int tb   = (blockIdx.x >> 1) * G;

    const uint32_t sb = smem_u32(sm);
    const uint32_t pb = mapa_u32(sb, rank ^ 1u);
    const uint32_t pA = pb + (uint32_t)offsetof(SM, A);
    const uint32_t pB = pb + (uint32_t)offsetof(SM, B);
    const uint32_t pD = pb + (uint32_t)offsetof(SM, D);

    const ulonglong2* WP = g_wp;

    // K-slice offsets for this (rank, q)
    const int r384 = (rank * 48 + q * 24) * 256;  // 384-row matrices
    const int r256 = (rank * 32 + q * 16) * 256;  // 256-row matrices
    const int a384 = rank * 192 + q * 96;         // act offset, 384 inputs
    const int a256 = rank * 128 + q * 64;         // act offset, 256 inputs

    // decoder mapping: sel 0..3 = (k-quarter, traj-pair)
    const int jd = tid & 127, sel = tid >> 7;
    const int gp = (sel & 1) * 2, kq = sel >> 1;

    float* out_prev = out;
    float* out_vol  = out + (size_t)NTRAJ * LATENT;
    float* out_dts  = out + (size_t)NTRAJ * LATENT + (size_t)NTRAJ * NSTEP * DEC_OUT;

    for (int i = tid; i < G * LATENT; i += THREADS) { sm->sy[i] = 0.f; sm->syt[i] = 0.f; }

    for (int t = 0; t < NTP; t++) {
        CLUSTER_SYNC();   // S0

        // ---- setup: xh -> syc tail, mask, dt ----
        {
            int g = tid >> 7, jj = tid & 127;
            sm->syc[g * GIN + LATENT + jj] =
                data[((size_t)(tb + g) * NTP + t) * (2 * INPUT) + jj];
        }
        if (warp < G) {
            const float* xp = data + ((size_t)(tb + warp) * NTP + t) * (2 * INPUT) + INPUT;
            float s = xp[lane] + xp[lane + 32] + xp[lane + 64] + xp[lane + 96];
#pragma unroll
            for (int off = 16; off; off >>= 1) s += __shfl_xor_sync(0xffffffffu, s, off);
            if (lane == 0) sm->smask[warp] = (s > 0.f) ? 1.f : 0.f;
        }
        if (tid < G && t > 0) {
            float d = ts[(size_t)(tb + tid) * NTP + t] - ts[(size_t)(tb + tid) * NTP + t - 1];
            sm->sdt[tid] = d;
            if (rank == 0)
                out_dts[(size_t)(tb + tid) * NSTEP + (t - 1)] = d;
        }
        __syncthreads();

        float u[G], ut[G];      // valid on q0 after S3
        float pdec[2], dtot[2]; // decoder partials

        if (t > 0) {
            // ---- decay layer1 (256->256) ----
            {
                const ulonglong2* Wd[1] = { WP + OFF_DK1 + r256 };
                float p[1][G];
                gemv_part<32, 1, 256, 4>(p, Wd, sm->sy + a256, LATENT, j);
                if (q)
                    *(float4*)&sm->P[0][j][0] = make_float4(p[0][0], p[0][1], p[0][2], p[0][3]);
                __syncthreads();
                if (!q) {
                    float4 lp = *(const float4*)&sm->P[0][j][0];
                    p[0][0] += lp.x; p[0][1] += lp.y; p[0][2] += lp.z; p[0][3] += lp.w;
                    st_peer_f4(pA + (uint32_t)(j * G * 4),
                               p[0][0], p[0][1], p[0][2], p[0][3]);
                }
                CLUSTER_SYNC();  // S1
                if (!q) {
                    float bv = dk_b1[j];
                    float4 pr = *(const float4*)&sm->A[0][j][0];
                    sm->shh0[0 * NUNITS + j] = fmaxf(p[0][0] + pr.x + bv, 0.f);
                    sm->shh0[1 * NUNITS + j] = fmaxf(p[0][1] + pr.y + bv, 0.f);
                    sm->shh0[2 * NUNITS + j] = fmaxf(p[0][2] + pr.z + bv, 0.f);
                    sm->shh0[3 * NUNITS + j] = fmaxf(p[0][3] + pr.w + bv, 0.f);
                }
                __syncthreads();
            }
            // ---- decay layer2: 256->1 (q0 warps) ----
            if (!q) {
                float v[G];
                float w2v = dk_w2[j];
#pragma unroll
                for (int g = 0; g < G; g++) v[g] = sm->shh0[g * NUNITS + j] * w2v;
#pragma unroll
                for (int off = 16; off; off >>= 1)
#pragma unroll
                    for (int g = 0; g < G; g++) v[g] += __shfl_xor_sync(0xffffffffu, v[g], off);
                if (lane == 0)
#pragma unroll
                    for (int g = 0; g < G; g++) sm->sred[warp][g] = v[g];
            }
            __syncthreads();
            if (tid < G) {
                float s = dk_b2[0];
#pragma unroll
                for (int w = 0; w < 8; w++) s += sm->sred[w][tid];
                sm->sdecay[tid] = fmaxf(s, 0.f);
            }
            __syncthreads();

            // ---- elementwise decay: 1024 items over 512 threads ----
            for (int it = tid; it < G * 256; it += THREADS) {
                int g = it >> 8, jj = it & 255;
                float d  = sm->sdecay[g] * sm->sdt[g];
                float e1 = __expf(-0.5f * d);
                float e2 = __expf(-d);
                float yv = sm->sy[g * LATENT + jj], ytv = sm->syt[g * LATENT + jj];
                float df = yv - ytv;
                sm->shh0[g * NUNITS + jj] = ytv + df * (0.5f * (1.f + e1));  // mean_ydec
                float yend = ytv + df * e2;
                sm->sy[g * LATENT + jj] = yend;
                sm->syc[g * GIN + jj]   = yend;
            }
            __syncthreads();

            // ---- decoder partial (K-quarter of mean_ydec) ----
            {
                const ulonglong2* Wd = WP + OFF_DEC + (rank * 32 + kq * 16) * 128;
                int ao = rank * 128 + kq * 64;
                gemv_dec2(pdec, Wd,
                          sm->shh0 + (gp + 0) * NUNITS + ao,
                          sm->shh0 + (gp + 1) * NUNITS + ao, jd);
                if (kq) {
                    sm->Pd[jd][gp + 0] = pdec[0];
                    sm->Pd[jd][gp + 1] = pdec[1];
                }
            }
        } else {
            for (int it = tid; it < G * 256; it += THREADS) {
                int g = it >> 8, jj = it & 255;
                sm->syc[g * GIN + jj] = 0.f;
            }
            __syncthreads();
        }

        // ---- fused gate layer1: ug/ugt/rg (384->256 x3) ----
        {
            const ulonglong2* Wg[3] = { WP + OFF_UG1  + r384,
                                        WP + OFF_UGT1 + r384,
                                        WP + OFF_RG1  + r384 };
            float p[3][G];
            gemv_part<48, 3, 256, 1>(p, Wg, sm->syc + a384, GIN, j);
            if (q) {
#pragma unroll
                for (int ng = 0; ng < 3; ng++)
                    *(float4*)&sm->P[ng][j][0] =
                        make_float4(p[ng][0], p[ng][1], p[ng][2], p[ng][3]);
            }
            __syncthreads();   // also publishes Pd (decoder) writes
            if (!q) {
#pragma unroll
                for (int ng = 0; ng < 3; ng++) {
                    float4 lp = *(const float4*)&sm->P[ng][j][0];
                    p[ng][0] += lp.x; p[ng][1] += lp.y; p[ng][2] += lp.z; p[ng][3] += lp.w;
                    st_peer_f4(pB + (uint32_t)((ng * 256 + j) * G * 4),
                               p[ng][0], p[ng][1], p[ng][2], p[ng][3]);
                }
                if (t > 0) {
                    dtot[0] = pdec[0] + sm->Pd[jd][gp + 0];
                    dtot[1] = pdec[1] + sm->Pd[jd][gp + 1];
                    if (rank == 1)
                        st_peer_f2(pD + (uint32_t)((jd * G + gp) * 4), dtot[0], dtot[1]);
                }
            }
            CLUSTER_SYNC();  // S2
            if (!q) {
                float b0 = ug_b1[j], b1 = ugt_b1[j], b2 = rg_b1[j];
                float4 r0 = *(const float4*)&sm->B[0][j][0];
                float4 r1 = *(const float4*)&sm->B[1][j][0];
                float4 r2 = *(const float4*)&sm->B[2][j][0];
                sm->shh0[0 * NUNITS + j] = tanhf(p[0][0] + r0.x + b0);
                sm->shh0[1 * NUNITS + j] = tanhf(p[0][1] + r0.y + b0);
                sm->shh0[2 * NUNITS + j] = tanhf(p[0][2] + r0.z + b0);
                sm->shh0[3 * NUNITS + j] = tanhf(p[0][3] + r0.w + b0);
                sm->shh1[0 * NUNITS + j] = tanhf(p[1][0] + r1.x + b1);
                sm->shh1[1 * NUNITS + j] = tanhf(p[1][1] + r1.y + b1);
                sm->shh1[2 * NUNITS + j] = tanhf(p[1][2] + r1.z + b1);
                sm->shh1[3 * NUNITS + j] = tanhf(p[1][3] + r1.w + b1);
                sm->shh2[0 * NUNITS + j] = tanhf(p[2][0] + r2.x + b2);
                sm->shh2[1 * NUNITS + j] = tanhf(p[2][1] + r2.y + b2);
                sm->shh2[2 * NUNITS + j] = tanhf(p[2][2] + r2.z + b2);
                sm->shh2[3 * NUNITS + j] = tanhf(p[2][3] + r2.w + b2);
                if (t > 0 && rank == 0) {
                    float bv = dec_b[jd];
                    out_vol[((size_t)(tb + gp + 0) * NSTEP + (t - 1)) * DEC_OUT + jd] =
                        dtot[0] + sm->D[jd][gp + 0] + bv;
                    out_vol[((size_t)(tb + gp + 1) * NSTEP + (t - 1)) * DEC_OUT + jd] =
                        dtot[1] + sm->D[jd][gp + 1] + bv;
                }
            }
            __syncthreads();
        }

        // ---- gate layer2 x3 (256->256), per-matrix acts ----
        {
            const ulonglong2* Wg[3] = { WP + OFF_UG2  + r256,
                                        WP + OFF_UGT2 + r256,
                                        WP + OFF_RG2  + r256 };
            const float* av[3] = { sm->shh0 + a256, sm->shh1 + a256, sm->shh2 + a256 };
            float p[3][G];
            gemv_part_ma<32, 3, 256>(p, Wg, av, NUNITS, j);
            if (q) {
#pragma unroll
                for (int ng = 0; ng < 3; ng++)
                    *(float4*)&sm->P[ng][j][0] =
                        make_float4(p[ng][0], p[ng][1], p[ng][2], p[ng][3]);
            }
            __syncthreads();
            if (!q) {
#pragma unroll
                for (int ng = 0; ng < 3; ng++) {
                    float4 lp = *(const float4*)&sm->P[ng][j][0];
                    p[ng][0] += lp.x; p[ng][1] += lp.y; p[ng][2] += lp.z; p[ng][3] += lp.w;
                    st_peer_f4(pA + (uint32_t)((ng * 256 + j) * G * 4),
                               p[ng][0], p[ng][1], p[ng][2], p[ng][3]);
                }
            }
            CLUSTER_SYNC();  // S3
            if (!q) {
                float b0 = ug_b2[j], b1 = ugt_b2[j], b2 = rg_b2[j];
                float4 r0 = *(const float4*)&sm->A[0][j][0];
                float4 r1 = *(const float4*)&sm->A[1][j][0];
                float4 r2 = *(const float4*)&sm->A[2][j][0];
                u[0]  = sigmoid_fast(p[0][0] + r0.x + b0);
                u[1]  = sigmoid_fast(p[0][1] + r0.y + b0);
                u[2]  = sigmoid_fast(p[0][2] + r0.z + b0);
                u[3]  = sigmoid_fast(p[0][3] + r0.w + b0);
                ut[0] = sigmoid_fast(p[1][0] + r1.x + b1);
                ut[1] = sigmoid_fast(p[1][1] + r1.y + b1);
                ut[2] = sigmoid_fast(p[1][2] + r1.z + b1);
                ut[3] = sigmoid_fast(p[1][3] + r1.w + b1);
                sm->syc[0 * GIN + j] *= sigmoid_fast(p[2][0] + r2.x + b2);
                sm->syc[1 * GIN + j] *= sigmoid_fast(p[2][1] + r2.y + b2);
                sm->syc[2 * GIN + j] *= sigmoid_fast(p[2][2] + r2.z + b2);
                sm->syc[3 * GIN + j] *= sigmoid_fast(p[2][3] + r2.w + b2);
            }
            __syncthreads();
        }

        // ---- new_state layer1 (384->256) ----
        {
            const ulonglong2* Wg[1] = { WP + OFF_NS1 + r384 };
            float p[1][G];
            gemv_part<48, 1, 256, 4>(p, Wg, sm->syc + a384, GIN, j);
            if (q)
                *(float4*)&sm->P[0][j][0] = make_float4(p[0][0], p[0][1], p[0][2], p[0][3]);
            __syncthreads();
            if (!q) {
                float4 lp = *(const float4*)&sm->P[0][j][0];
                p[0][0] += lp.x; p[0][1] += lp.y; p[0][2] += lp.z; p[0][3] += lp.w;
                st_peer_f4(pB + (uint32_t)(j * G * 4),
                           p[0][0], p[0][1], p[0][2], p[0][3]);
            }
            CLUSTER_SYNC();  // S4
            if (!q) {
                float bv = ns_b1[j];
                float4 pr = *(const float4*)&sm->B[0][j][0];
                sm->shh0[0 * NUNITS + j] = tanhf(p[0][0] + pr.x + bv);
                sm->shh0[1 * NUNITS + j] = tanhf(p[0][1] + pr.y + bv);
                sm->shh0[2 * NUNITS + j] = tanhf(p[0][2] + pr.z + bv);
                sm->shh0[3 * NUNITS + j] = tanhf(p[0][3] + pr.w + bv);
            }
            __syncthreads();
        }

        // ---- new_state layer2 (256->256) + masked update ----
        {
            const ulonglong2* Wg[1] = { WP + OFF_NS2 + r256 };
            float p[1][G];
            gemv_part<32, 1, 256, 4>(p, Wg, sm->shh0 + a256, NUNITS, j);
            if (q)
                *(float4*)&sm->P[0][j][0] = make_float4(p[0][0], p[0][1], p[0][2], p[0][3]);
            __syncthreads();
            if (!q) {
                float4 lp = *(const float4*)&sm->P[0][j][0];
                p[0][0] += lp.x; p[0][1] += lp.y; p[0][2] += lp.z; p[0][3] += lp.w;
                st_peer_f4(pA + (uint32_t)(j * G * 4),
                           p[0][0], p[0][1], p[0][2], p[0][3]);
            }
            CLUSTER_SYNC();  // S5
            if (!q) {
                float bv = ns_b2[j];
                float4 pr = *(const float4*)&sm->A[0][j][0];
                float prv[G] = { pr.x, pr.y, pr.z, pr.w };
#pragma unroll
                for (int g = 0; g < G; g++) {
                    float nsv  = p[0][g] + prv[g] + bv;
                    float m    = sm->smask[g];
                    float yend = sm->sy[g * LATENT + j], ytv = sm->syt[g * LATENT + j];
                    float ny   = (1.f - u[g])  * nsv + u[g]  * yend;
                    float nyt  = (1.f - ut[g]) * nsv + ut[g] * ytv;
                    sm->sy [g * LATENT + j] = m * ny  + (1.f - m) * yend;
                    sm->syt[g * LATENT + j] = m * nyt + (1.f - m) * ytv;
                }
            }
        }
        // S0 of next iteration publishes sy/syt and protects buffer reuse
    }

    CLUSTER_SYNC();
    if (rank == 0 && !q) {
#pragma unroll
        for (int g = 0; g < G; g++)
            out_prev[(size_t)(tb + g) * LATENT + j] = sm->sy[g * LATENT + j];
    }
}

extern "C" void kernel_launch(void* const* d_in, const int* in_sizes, int n_in,
                              void* d_out, int out_size) {
    const float* data   = (const float*)d_in[0];
    const float* ts     = (const float*)d_in[1];
    const float* ug_w1  = (const float*)d_in[2];
    const float* ug_b1  = (const float*)d_in[3];
    const float* ug_w2  = (const float*)d_in[4];
    const float* ug_b2  = (const float*)d_in[5];
    const float* ugt_w1 = (const float*)d_in[6];
    const float* ugt_b1 = (const float*)d_in[7];
    const float* ugt_w2 = (const float*)d_in[8];
    const float* ugt_b2 = (const float*)d_in[9];
    const float* rg_w1  = (const float*)d_in[10];
    const float* rg_b1  = (const float*)d_in[11];
    const float* rg_w2  = (const float*)d_in[12];
    const float* rg_b2  = (const float*)d_in[13];
    // d_in[14..17] = rgt_* : unused by the reference
    const float* ns_w1  = (const float*)d_in[18];
    const float* ns_b1  = (const float*)d_in[19];
    const float* ns_w2  = (const float*)d_in[20];
    const float* ns_b2  = (const float*)d_in[21];
    const float* dk_w1  = (const float*)d_in[22];
    const float* dk_b1  = (const float*)d_in[23];
    const float* dk_w2  = (const float*)d_in[24];
    const float* dk_b2  = (const float*)d_in[25];
    const float* dec_w  = (const float*)d_in[26];
    const float* dec_b  = (const float*)d_in[27];

    cudaFuncSetAttribute(rnn_decay_kernel,
                         cudaFuncAttributeMaxDynamicSharedMemorySize, SMEM_BYTES);

    pack_kernel<<<(WP_TOTAL + 255) / 256, 256>>>(
        ug_w1, ugt_w1, rg_w1, ns_w1, ug_w2, ugt_w2, rg_w2, ns_w2, dk_w1, dec_w);

    rnn_decay_kernel<<<NBLK, THREADS, SMEM_BYTES>>>(
        data, ts,
        ug_b1, ug_b2, ugt_b1, ugt_b2, rg_b1, rg_b2,
        ns_b1, ns_b2, dk_b1, dk_w2, dk_b2, dec_b,
        (float*)d_out);
}